// round 9
// baseline (speedup 1.0000x reference)
#include <cuda_runtime.h>
#include <cuda_bf16.h>
#include <cstdint>

#define B_  32
#define T_  1024
#define S_  1024
#define D_  512
#define K2_ 1024          // 2*D
#define M_  (B_ * T_)     // 32768

// GEMM tiling
#define BM 128
#define BN 256
#define BKc 16            // k per chunk (one m16n8k16 k-step)
#define NCH (K2_ / BKc)   // 64 chunks
#define NSTAGE 5
#define NTHREADS 512

// smem layout (bytes, per stage): rows padded to 48B for conflict-free ldmatrix
#define A_ROW   48
#define A_HI_OFF 0
#define A_LO_OFF (128 * A_ROW)            // 6144
#define W_HI_OFF (2 * 128 * A_ROW)        // 12288
#define W_LO_OFF (W_HI_OFF + 256 * A_ROW) // 24576
#define STAGE_SZ (W_LO_OFF + 256 * A_ROW) // 36864
#define SMEM_TOTAL (NSTAGE * STAGE_SZ)    // 184320

// ---------------------------------------------------------------------------
// device scratch (module globals)
// ---------------------------------------------------------------------------
__device__ int d_j[M_];
__device__ __align__(16) __nv_bfloat16 d_Whi[D_ * K2_];
__device__ __align__(16) __nv_bfloat16 d_Wlo[D_ * K2_];
__device__ __align__(16) __nv_bfloat16 d_Ahi[(size_t)M_ * K2_];
__device__ __align__(16) __nv_bfloat16 d_Alo[(size_t)M_ * K2_];

// ---------------------------------------------------------------------------
// PTX helpers
// ---------------------------------------------------------------------------
__device__ __forceinline__ uint32_t smem_u32(const void* p) {
    uint32_t a;
    asm("{ .reg .u64 t; cvta.to.shared.u64 t, %1; cvt.u32.u64 %0, t; }"
        : "=r"(a) : "l"(p));
    return a;
}
__device__ __forceinline__ void cp16(uint32_t dst, const void* src) {
    asm volatile("cp.async.cg.shared.global [%0], [%1], 16;" :: "r"(dst), "l"(src));
}
#define CP_COMMIT() asm volatile("cp.async.commit_group;" ::: "memory")
#define CP_WAIT(n)  asm volatile("cp.async.wait_group %0;" :: "n"(n) : "memory")

__device__ __forceinline__ void ldsm4(uint32_t* r, uint32_t addr) {
    asm volatile("ldmatrix.sync.aligned.m8n8.x4.shared.b16 {%0,%1,%2,%3}, [%4];"
                 : "=r"(r[0]), "=r"(r[1]), "=r"(r[2]), "=r"(r[3]) : "r"(addr));
}
__device__ __forceinline__ void mma16816(float* c, const uint32_t* a,
                                         uint32_t b0, uint32_t b1) {
    asm volatile(
        "mma.sync.aligned.m16n8k16.row.col.f32.bf16.bf16.f32 "
        "{%0,%1,%2,%3}, {%4,%5,%6,%7}, {%8,%9}, {%0,%1,%2,%3};"
        : "+f"(c[0]), "+f"(c[1]), "+f"(c[2]), "+f"(c[3])
        : "r"(a[0]), "r"(a[1]), "r"(a[2]), "r"(a[3]), "r"(b0), "r"(b1));
}
__device__ __forceinline__ void split_bf16(float v, __nv_bfloat16& h, __nv_bfloat16& l) {
    h = __float2bfloat16(v);
    l = __float2bfloat16(v - __bfloat162float(h));
}

// ---------------------------------------------------------------------------
// 1) j indices (token buffer int32 or int64 — detected on device)
// ---------------------------------------------------------------------------
__global__ void compute_j_kernel(const int* __restrict__ w32) {
    __shared__ int s[T_];
    __shared__ int is64_s;
    const int b = blockIdx.x;
    const int t = threadIdx.x;
    if (t == 0) {
        int allzero = 1;
        #pragma unroll
        for (int i = 1; i < 64; i += 2) allzero &= (w32[i] == 0);
        is64_s = allzero;
    }
    __syncthreads();
    const int idx = b * T_ + t;
    const int tok = is64_s ? w32[idx * 2] : w32[idx];
    int flag = (t >= 1 && (tok == 1 || tok == 2)) ? 1 : 0;
    s[t] = flag;
    __syncthreads();
    #pragma unroll
    for (int off = 1; off < T_; off <<= 1) {
        int v = (t >= off) ? s[t - off] : 0;
        __syncthreads();
        s[t] += v;
        __syncthreads();
    }
    int jj;
    if (t == 0) jj = 0;
    else { jj = t - s[t] - 1; if (jj < 0) jj += S_; }
    d_j[idx] = jj;
}

// ---------------------------------------------------------------------------
// 2) attn: write one-hot rows directly (fused zero+scatter, pure streaming)
// ---------------------------------------------------------------------------
__global__ void write_attn_kernel(float* __restrict__ attn) {
    const int m = blockIdx.x;
    const int t = threadIdx.x;          // 256 threads x float4 = 1024 cols
    const int j = d_j[m];
    float4 v = make_float4(0.f, 0.f, 0.f, 0.f);
    if ((j >> 2) == t) ((float*)&v)[j & 3] = 1.0f;
    ((float4*)(attn + (size_t)m * S_))[t] = v;
}

// ---------------------------------------------------------------------------
// 3) prep: W -> bf16 hi/lo; A -> bf16 hi/lo (gathered rows)
// ---------------------------------------------------------------------------
__global__ void prep_w_kernel(const float* __restrict__ W) {
    const int n = blockIdx.x;
    const int col = threadIdx.x * 4;
    float4 v = *(const float4*)(W + (size_t)n * K2_ + col);
    __nv_bfloat16 hx, hy, hz, hw, lx, ly, lz, lw;
    split_bf16(v.x, hx, lx); split_bf16(v.y, hy, ly);
    split_bf16(v.z, hz, lz); split_bf16(v.w, hw, lw);
    union { __nv_bfloat162 h2[2]; uint2 u; } ph, pl;
    ph.h2[0] = __halves2bfloat162(hx, hy); ph.h2[1] = __halves2bfloat162(hz, hw);
    pl.h2[0] = __halves2bfloat162(lx, ly); pl.h2[1] = __halves2bfloat162(lz, lw);
    *(uint2*)(d_Whi + (size_t)n * K2_ + col) = ph.u;
    *(uint2*)(d_Wlo + (size_t)n * K2_ + col) = pl.u;
}

__global__ void prep_a_kernel(const float* __restrict__ outp,     // [M, D]
                              const float* __restrict__ context)  // [B, S, D]
{
    const int m = blockIdx.x;
    const int t = threadIdx.x;        // 256 threads x 4 floats = 1024 cols
    const int col = t * 4;
    const int bb = m >> 10;
    const int jm = d_j[m];
    const float* src = (t < 128)
        ? context + ((size_t)((bb << 10) + jm)) * D_ + col
        : outp + (size_t)m * D_ + (col - D_);
    float4 v = *(const float4*)src;
    __nv_bfloat16 hx, hy, hz, hw, lx, ly, lz, lw;
    split_bf16(v.x, hx, lx); split_bf16(v.y, hy, ly);
    split_bf16(v.z, hz, lz); split_bf16(v.w, hw, lw);
    union { __nv_bfloat162 h2[2]; uint2 u; } ph, pl;
    ph.h2[0] = __halves2bfloat162(hx, hy); ph.h2[1] = __halves2bfloat162(hz, hw);
    pl.h2[0] = __halves2bfloat162(lx, ly); pl.h2[1] = __halves2bfloat162(lz, lw);
    *(uint2*)(d_Ahi + (size_t)m * K2_ + col) = ph.u;
    *(uint2*)(d_Alo + (size_t)m * K2_ + col) = pl.u;
}

// ---------------------------------------------------------------------------
// 4) HMMA GEMM: out[m,n] = tanh(bias[n] + sum_k A[m,k]*W[n,k])
//    3-pass bf16 split, CTA 128x256, 16 warps (warp tile 64x32),
//    K-chunk 16, 5-stage cp.async pipeline, one __syncthreads per chunk.
// ---------------------------------------------------------------------------
__global__ __launch_bounds__(NTHREADS, 1)
void gemm_mma_kernel(const float* __restrict__ bias, float* __restrict__ out)
{
    extern __shared__ char smem[];
    const uint32_t smb = smem_u32(smem);
    const int tid = threadIdx.x;
    const int wid = tid >> 5;
    const int lane = tid & 31;
    const int wm = wid & 1;           // warp m (2): 64 rows each
    const int wn = wid >> 1;          // warp n (8): 32 cols each
    const int m0 = blockIdx.y * BM;
    const int n0 = blockIdx.x * BN;

    float acc[4][4][4];               // [mt][n8][frag] : 64x32 warp tile
    #pragma unroll
    for (int i = 0; i < 4; i++)
        #pragma unroll
        for (int j = 0; j < 4; j++)
            #pragma unroll
            for (int k = 0; k < 4; k++) acc[i][j][k] = 0.f;

    // ---- loader: stage s <- chunk c  (512 threads: 0-255 A, 256-511 W)
    auto issue = [&](int c, int s) {
        const int k0 = c * BKc;
        const uint32_t st = smb + s * STAGE_SZ;
        if (tid < 256) {
            const int half = tid >> 7;
            const int r = tid & 127;
            const __nv_bfloat16* src =
                (half ? d_Alo : d_Ahi) + (size_t)(m0 + r) * K2_ + k0;
            const uint32_t dst = st + (half ? A_LO_OFF : A_HI_OFF) + r * A_ROW;
            cp16(dst,      src);
            cp16(dst + 16, src + 8);
        } else {
            const int r = tid - 256;
            const __nv_bfloat16* sh = d_Whi + (size_t)(n0 + r) * K2_ + k0;
            const __nv_bfloat16* sl = d_Wlo + (size_t)(n0 + r) * K2_ + k0;
            const uint32_t dh = st + W_HI_OFF + r * A_ROW;
            const uint32_t dl = st + W_LO_OFF + r * A_ROW;
            cp16(dh, sh); cp16(dh + 16, sh + 8);
            cp16(dl, sl); cp16(dl + 16, sl + 8);
        }
    };

    // prologue: fill stages 0..3 (one stage of write slack)
    #pragma unroll
    for (int s = 0; s < NSTAGE - 1; s++) { issue(s, s); CP_COMMIT(); }

    // ldmatrix lane addressing
    const uint32_t aoff = (uint32_t)((wm * 64 + (lane & 15)) * A_ROW + (lane >> 4) * 16);
    const int g = lane >> 3;
    const uint32_t boff = (uint32_t)((wn * 32 + ((g >> 1) << 3) + (lane & 7)) * A_ROW
                                     + (g & 1) * 16);

    int stage = 0;
    int wstage = NSTAGE - 1;
    for (int c = 0; c < NCH; c++) {
        CP_WAIT(3);
        __syncthreads();
        // refill the stage consumed at iter c-1 (all warps passed the sync)
        if (c + NSTAGE - 1 < NCH) issue(c + NSTAGE - 1, wstage);
        CP_COMMIT();

        const uint32_t st = smb + stage * STAGE_SZ;
        #pragma unroll
        for (int np = 0; np < 2; np++) {
            uint32_t bh[4], bl[4];
            ldsm4(bh, st + W_HI_OFF + boff + np * 16 * A_ROW);
            ldsm4(bl, st + W_LO_OFF + boff + np * 16 * A_ROW);
            #pragma unroll
            for (int mt = 0; mt < 4; mt++) {
                uint32_t ah[4], al[4];
                ldsm4(ah, st + A_HI_OFF + aoff + mt * 16 * A_ROW);
                ldsm4(al, st + A_LO_OFF + aoff + mt * 16 * A_ROW);
                float* a0 = acc[mt][np * 2];
                float* a1 = acc[mt][np * 2 + 1];
                mma16816(a0, ah, bh[0], bh[1]);   // Ah*Wh
                mma16816(a1, ah, bh[2], bh[3]);
                mma16816(a0, ah, bl[0], bl[1]);   // Ah*Wl
                mma16816(a1, ah, bl[2], bl[3]);
                mma16816(a0, al, bh[0], bh[1]);   // Al*Wh
                mma16816(a1, al, bh[2], bh[3]);
            }
        }

        stage  = (stage  + 1 == NSTAGE) ? 0 : stage + 1;
        wstage = (wstage + 1 == NSTAGE) ? 0 : wstage + 1;
    }

    // ---- epilogue: bias + tanh, float2 stores
    const int r4 = lane >> 2;
    const int c2 = (lane & 3) * 2;
    #pragma unroll
    for (int mt = 0; mt < 4; mt++) {
        #pragma unroll
        for (int nt = 0; nt < 4; nt++) {
            const int gm = m0 + wm * 64 + mt * 16 + r4;
            const int gn = n0 + wn * 32 + nt * 8 + c2;
            const float b0 = bias[gn], b1 = bias[gn + 1];
            float2 v0, v1;
            v0.x = tanhf(acc[mt][nt][0] + b0);
            v0.y = tanhf(acc[mt][nt][1] + b1);
            v1.x = tanhf(acc[mt][nt][2] + b0);
            v1.y = tanhf(acc[mt][nt][3] + b1);
            *(float2*)(out + (size_t)gm * D_ + gn) = v0;
            *(float2*)(out + (size_t)(gm + 8) * D_ + gn) = v1;
        }
    }
}

// ---------------------------------------------------------------------------
extern "C" void kernel_launch(void* const* d_in, const int* in_sizes, int n_in,
                              void* d_out, int out_size) {
    const int* input_var = nullptr;
    const float* output  = nullptr;
    const float* context = nullptr;
    const float* W    = nullptr;
    const float* bias = nullptr;

    for (int i = 0; i < n_in; i++) {
        const int sz = in_sizes[i];
        if (sz == B_ * T_) input_var = (const int*)d_in[i];
        else if (sz == B_ * T_ * D_) {
            if (!output) output = (const float*)d_in[i];
            else if (!context) context = (const float*)d_in[i];
        } else if (sz == D_ * K2_) W = (const float*)d_in[i];
        else if (sz == D_) bias = (const float*)d_in[i];
    }

    float* out  = (float*)d_out;                 // [B,T,D]
    float* attn = out + (size_t)M_ * D_;         // [B,T,S]

    static bool attr_set = false;
    if (!attr_set) {
        cudaFuncSetAttribute(gemm_mma_kernel,
                             cudaFuncAttributeMaxDynamicSharedMemorySize, SMEM_TOTAL);
        attr_set = true;
    }

    // gemm placed at call-index 3 so ncu (-s 5 -c 1) captures it
    compute_j_kernel<<<B_, T_>>>(input_var);
    prep_w_kernel<<<D_, 256>>>(W);
    prep_a_kernel<<<M_, 256>>>(output, context);
    dim3 grid(D_ / BN, M_ / BM);  // (2, 256)
    gemm_mma_kernel<<<grid, NTHREADS, SMEM_TOTAL>>>(bias, out);
    write_attn_kernel<<<M_, 256>>>(attn);
}

// round 10
// speedup vs baseline: 1.3631x; 1.3631x over previous
#include <cuda_runtime.h>
#include <cuda_fp16.h>
#include <cstdint>

#define B_  32
#define T_  1024
#define S_  1024
#define D_  512
#define K2_ 1024          // 2*D
#define M_  (B_ * T_)     // 32768

// GEMM tiling
#define BM 128
#define BN 256
#define BKc 16            // k per chunk (one m16n8k16 k-step)
#define NCH (K2_ / BKc)   // 64 chunks
#define NSTAGE 5
#define NTHREADS 256

// smem layout (bytes, per stage): rows padded to 48B for conflict-free ldmatrix
#define A_ROW   48
#define A_OFF   0
#define W_OFF   (128 * A_ROW)             // 6144
#define STAGE_SZ (W_OFF + 256 * A_ROW)    // 18432
#define SMEM_TOTAL (NSTAGE * STAGE_SZ)    // 92160

// ---------------------------------------------------------------------------
// device scratch (module globals)
// ---------------------------------------------------------------------------
__device__ int d_j[M_];
__device__ __align__(16) __half d_W16[D_ * K2_];
__device__ __align__(16) __half d_A16[(size_t)M_ * K2_];

// ---------------------------------------------------------------------------
// PTX helpers
// ---------------------------------------------------------------------------
__device__ __forceinline__ uint32_t smem_u32(const void* p) {
    uint32_t a;
    asm("{ .reg .u64 t; cvta.to.shared.u64 t, %1; cvt.u32.u64 %0, t; }"
        : "=r"(a) : "l"(p));
    return a;
}
__device__ __forceinline__ void cp16(uint32_t dst, const void* src) {
    asm volatile("cp.async.cg.shared.global [%0], [%1], 16;" :: "r"(dst), "l"(src));
}
#define CP_COMMIT() asm volatile("cp.async.commit_group;" ::: "memory")
#define CP_WAIT(n)  asm volatile("cp.async.wait_group %0;" :: "n"(n) : "memory")

__device__ __forceinline__ void ldsm4(uint32_t* r, uint32_t addr) {
    asm volatile("ldmatrix.sync.aligned.m8n8.x4.shared.b16 {%0,%1,%2,%3}, [%4];"
                 : "=r"(r[0]), "=r"(r[1]), "=r"(r[2]), "=r"(r[3]) : "r"(addr));
}
__device__ __forceinline__ void mma16816(float* c, const uint32_t* a,
                                         uint32_t b0, uint32_t b1) {
    asm volatile(
        "mma.sync.aligned.m16n8k16.row.col.f32.f16.f16.f32 "
        "{%0,%1,%2,%3}, {%4,%5,%6,%7}, {%8,%9}, {%0,%1,%2,%3};"
        : "+f"(c[0]), "+f"(c[1]), "+f"(c[2]), "+f"(c[3])
        : "r"(a[0]), "r"(a[1]), "r"(a[2]), "r"(a[3]), "r"(b0), "r"(b1));
}

// ---------------------------------------------------------------------------
// 1) j indices (token buffer int32 or int64 — detected on device)
// ---------------------------------------------------------------------------
__global__ void compute_j_kernel(const int* __restrict__ w32) {
    __shared__ int s[T_];
    __shared__ int is64_s;
    const int b = blockIdx.x;
    const int t = threadIdx.x;
    if (t == 0) {
        int allzero = 1;
        #pragma unroll
        for (int i = 1; i < 64; i += 2) allzero &= (w32[i] == 0);
        is64_s = allzero;
    }
    __syncthreads();
    const int idx = b * T_ + t;
    const int tok = is64_s ? w32[idx * 2] : w32[idx];
    int flag = (t >= 1 && (tok == 1 || tok == 2)) ? 1 : 0;
    s[t] = flag;
    __syncthreads();
    #pragma unroll
    for (int off = 1; off < T_; off <<= 1) {
        int v = (t >= off) ? s[t - off] : 0;
        __syncthreads();
        s[t] += v;
        __syncthreads();
    }
    int jj;
    if (t == 0) jj = 0;
    else { jj = t - s[t] - 1; if (jj < 0) jj += S_; }
    d_j[idx] = jj;
}

// ---------------------------------------------------------------------------
// 2) attn: write one-hot rows directly (fused zero+scatter, pure streaming)
// ---------------------------------------------------------------------------
__global__ void write_attn_kernel(float* __restrict__ attn) {
    const int m = blockIdx.x;
    const int t = threadIdx.x;          // 256 threads x float4 = 1024 cols
    const int j = d_j[m];
    float4 v = make_float4(0.f, 0.f, 0.f, 0.f);
    if ((j >> 2) == t) ((float*)&v)[j & 3] = 1.0f;
    ((float4*)(attn + (size_t)m * S_))[t] = v;
}

// ---------------------------------------------------------------------------
// 3) prep: W -> fp16 [n][k]; A -> fp16 (gathered [context | output] rows)
// ---------------------------------------------------------------------------
__global__ void prep_w_kernel(const float* __restrict__ W) {
    const int n = blockIdx.x;
    const int col = threadIdx.x * 4;
    float4 v = *(const float4*)(W + (size_t)n * K2_ + col);
    union { __half2 h2[2]; uint2 u; } p;
    p.h2[0] = __floats2half2_rn(v.x, v.y);
    p.h2[1] = __floats2half2_rn(v.z, v.w);
    *(uint2*)(d_W16 + (size_t)n * K2_ + col) = p.u;
}

__global__ void prep_a_kernel(const float* __restrict__ outp,     // [M, D]
                              const float* __restrict__ context)  // [B, S, D]
{
    const int m = blockIdx.x;
    const int t = threadIdx.x;        // 256 threads x 4 floats = 1024 cols
    const int col = t * 4;
    const int bb = m >> 10;
    const int jm = d_j[m];
    const float* src = (t < 128)
        ? context + ((size_t)((bb << 10) + jm)) * D_ + col
        : outp + (size_t)m * D_ + (col - D_);
    float4 v = *(const float4*)src;
    union { __half2 h2[2]; uint2 u; } p;
    p.h2[0] = __floats2half2_rn(v.x, v.y);
    p.h2[1] = __floats2half2_rn(v.z, v.w);
    *(uint2*)(d_A16 + (size_t)m * K2_ + col) = p.u;
}

// ---------------------------------------------------------------------------
// 4) HMMA GEMM (single-pass fp16, fp32 accum):
//    out[m,n] = tanh(bias[n] + sum_k A[m,k]*W[n,k])
//    CTA 128x256, 8 warps 64x64, K-chunk 16, 5-stage pipeline, 1 sync/chunk.
// ---------------------------------------------------------------------------
__global__ __launch_bounds__(NTHREADS, 1)
void gemm_mma_kernel(const float* __restrict__ bias, float* __restrict__ out)
{
    extern __shared__ char smem[];
    const uint32_t smb = smem_u32(smem);
    const int tid = threadIdx.x;
    const int wid = tid >> 5;
    const int lane = tid & 31;
    const int wm = wid & 1;           // warp m (2): 64 rows
    const int wn = wid >> 1;          // warp n (4): 64 cols
    const int m0 = blockIdx.y * BM;
    const int n0 = blockIdx.x * BN;

    float acc[4][8][4];
    #pragma unroll
    for (int i = 0; i < 4; i++)
        #pragma unroll
        for (int j = 0; j < 8; j++)
            #pragma unroll
            for (int k = 0; k < 4; k++) acc[i][j][k] = 0.f;

    // ---- loader: stage s <- chunk c (256 threads)
    auto issue = [&](int c, int s) {
        const int k0 = c * BKc;
        const uint32_t st = smb + s * STAGE_SZ;
        // A: 128 rows x 32B (tids 0-127, 2x cp16 each)
        if (tid < 128) {
            const __half* src = d_A16 + (size_t)(m0 + tid) * K2_ + k0;
            const uint32_t dst = st + A_OFF + tid * A_ROW;
            cp16(dst,      src);
            cp16(dst + 16, src + 8);
        }
        // W: 256 rows x 32B (all 256 tids, 2x cp16 each)
        {
            const __half* src = d_W16 + (size_t)(n0 + tid) * K2_ + k0;
            const uint32_t dst = st + W_OFF + tid * A_ROW;
            cp16(dst,      src);
            cp16(dst + 16, src + 8);
        }
    };

    // prologue: fill stages 0..3 (one stage of write slack)
    #pragma unroll
    for (int s = 0; s < NSTAGE - 1; s++) { issue(s, s); CP_COMMIT(); }

    // ldmatrix lane addressing
    const uint32_t aoff = (uint32_t)((wm * 64 + (lane & 15)) * A_ROW + (lane >> 4) * 16);
    const int g = lane >> 3;
    const uint32_t boff = (uint32_t)((wn * 64 + ((g >> 1) << 3) + (lane & 7)) * A_ROW
                                     + (g & 1) * 16);

    int stage = 0;
    int wstage = NSTAGE - 1;
    for (int c = 0; c < NCH; c++) {
        CP_WAIT(3);
        __syncthreads();
        // refill the stage consumed at iter c-1 (all warps passed the sync)
        if (c + NSTAGE - 1 < NCH) issue(c + NSTAGE - 1, wstage);
        CP_COMMIT();

        const uint32_t st = smb + stage * STAGE_SZ;
        uint32_t a[4][4];
        #pragma unroll
        for (int mt = 0; mt < 4; mt++)
            ldsm4(a[mt], st + A_OFF + aoff + mt * 16 * A_ROW);
        #pragma unroll
        for (int np = 0; np < 4; np++) {
            uint32_t b[4];
            ldsm4(b, st + W_OFF + boff + np * 16 * A_ROW);
            #pragma unroll
            for (int mt = 0; mt < 4; mt++) {
                mma16816(acc[mt][np * 2],     a[mt], b[0], b[1]);
                mma16816(acc[mt][np * 2 + 1], a[mt], b[2], b[3]);
            }
        }

        stage  = (stage  + 1 == NSTAGE) ? 0 : stage + 1;
        wstage = (wstage + 1 == NSTAGE) ? 0 : wstage + 1;
    }

    // ---- epilogue: bias + tanh, float2 stores
    const int r4 = lane >> 2;
    const int c2 = (lane & 3) * 2;
    #pragma unroll
    for (int mt = 0; mt < 4; mt++) {
        #pragma unroll
        for (int nt = 0; nt < 8; nt++) {
            const int gm = m0 + wm * 64 + mt * 16 + r4;
            const int gn = n0 + wn * 64 + nt * 8 + c2;
            const float b0 = bias[gn], b1 = bias[gn + 1];
            float2 v0, v1;
            v0.x = tanhf(acc[mt][nt][0] + b0);
            v0.y = tanhf(acc[mt][nt][1] + b1);
            v1.x = tanhf(acc[mt][nt][2] + b0);
            v1.y = tanhf(acc[mt][nt][3] + b1);
            *(float2*)(out + (size_t)gm * D_ + gn) = v0;
            *(float2*)(out + (size_t)(gm + 8) * D_ + gn) = v1;
        }
    }
}

// ---------------------------------------------------------------------------
extern "C" void kernel_launch(void* const* d_in, const int* in_sizes, int n_in,
                              void* d_out, int out_size) {
    const int* input_var = nullptr;
    const float* output  = nullptr;
    const float* context = nullptr;
    const float* W    = nullptr;
    const float* bias = nullptr;

    for (int i = 0; i < n_in; i++) {
        const int sz = in_sizes[i];
        if (sz == B_ * T_) input_var = (const int*)d_in[i];
        else if (sz == B_ * T_ * D_) {
            if (!output) output = (const float*)d_in[i];
            else if (!context) context = (const float*)d_in[i];
        } else if (sz == D_ * K2_) W = (const float*)d_in[i];
        else if (sz == D_) bias = (const float*)d_in[i];
    }

    float* out  = (float*)d_out;                 // [B,T,D]
    float* attn = out + (size_t)M_ * D_;         // [B,T,S]

    static bool attr_set = false;
    if (!attr_set) {
        cudaFuncSetAttribute(gemm_mma_kernel,
                             cudaFuncAttributeMaxDynamicSharedMemorySize, SMEM_TOTAL);
        attr_set = true;
    }

    // gemm placed at call-index 3 so ncu (-s 5 -c 1) captures it
    compute_j_kernel<<<B_, T_>>>(input_var);
    prep_w_kernel<<<D_, 256>>>(W);
    prep_a_kernel<<<M_, 256>>>(output, context);
    dim3 grid(D_ / BN, M_ / BM);  // (2, 256)
    gemm_mma_kernel<<<grid, NTHREADS, SMEM_TOTAL>>>(bias, out);
    write_attn_kernel<<<M_, 256>>>(attn);
}

// round 11
// speedup vs baseline: 1.8767x; 1.3768x over previous
#include <cuda_runtime.h>
#include <cuda_fp16.h>
#include <cstdint>

#define B_  32
#define T_  1024
#define S_  1024
#define D_  512
#define K2_ 1024          // 2*D
#define M_  (B_ * T_)     // 32768

// GEMM tiling
#define BM 128
#define BN 256
#define BKc 32            // k per chunk (two m16n8k16 k-steps)
#define NCH (K2_ / BKc)   // 32 chunks
#define NSTAGE 5
#define NTHREADS 256

// smem layout (bytes, per stage): 64B data + 16B pad = 80B row stride
// (conflict-free ldsm: r*80 -> word offsets {0,20,8,28,16,4,24,12} mod 32)
#define A_ROW   80
#define A_OFF   0
#define W_OFF   (128 * A_ROW)             // 10240
#define STAGE_SZ (W_OFF + 256 * A_ROW)    // 30720
#define SMEM_TOTAL (NSTAGE * STAGE_SZ)    // 153600

// ---------------------------------------------------------------------------
// device scratch (module globals)
// ---------------------------------------------------------------------------
__device__ int d_j[M_];
__device__ __align__(16) __half d_W16[D_ * K2_];
__device__ __align__(16) __half d_A16[(size_t)M_ * K2_];

// ---------------------------------------------------------------------------
// PTX helpers
// ---------------------------------------------------------------------------
__device__ __forceinline__ uint32_t smem_u32(const void* p) {
    uint32_t a;
    asm("{ .reg .u64 t; cvta.to.shared.u64 t, %1; cvt.u32.u64 %0, t; }"
        : "=r"(a) : "l"(p));
    return a;
}
__device__ __forceinline__ void cp16(uint32_t dst, const void* src) {
    asm volatile("cp.async.cg.shared.global [%0], [%1], 16;" :: "r"(dst), "l"(src));
}
#define CP_COMMIT() asm volatile("cp.async.commit_group;" ::: "memory")
#define CP_WAIT(n)  asm volatile("cp.async.wait_group %0;" :: "n"(n) : "memory")

__device__ __forceinline__ void ldsm4(uint32_t* r, uint32_t addr) {
    asm volatile("ldmatrix.sync.aligned.m8n8.x4.shared.b16 {%0,%1,%2,%3}, [%4];"
                 : "=r"(r[0]), "=r"(r[1]), "=r"(r[2]), "=r"(r[3]) : "r"(addr));
}
__device__ __forceinline__ void mma16816(float* c, const uint32_t* a,
                                         uint32_t b0, uint32_t b1) {
    asm volatile(
        "mma.sync.aligned.m16n8k16.row.col.f32.f16.f16.f32 "
        "{%0,%1,%2,%3}, {%4,%5,%6,%7}, {%8,%9}, {%0,%1,%2,%3};"
        : "+f"(c[0]), "+f"(c[1]), "+f"(c[2]), "+f"(c[3])
        : "r"(a[0]), "r"(a[1]), "r"(a[2]), "r"(a[3]), "r"(b0), "r"(b1));
}

// ---------------------------------------------------------------------------
// 1) merged: compute_j (blocks 0..31) + prep_w (blocks 32..543)
// ---------------------------------------------------------------------------
__global__ void prep_misc_kernel(const int* __restrict__ w32,
                                 const float* __restrict__ W) {
    const int bid = blockIdx.x;
    const int t = threadIdx.x;
    if (bid < B_) {
        // --- j indices (token buffer int32 or int64, detected on device)
        __shared__ int s[T_];
        __shared__ int is64_s;
        if (t == 0) {
            int allzero = 1;
            #pragma unroll
            for (int i = 1; i < 64; i += 2) allzero &= (w32[i] == 0);
            is64_s = allzero;
        }
        __syncthreads();
        const int idx = bid * T_ + t;
        const int tok = is64_s ? w32[idx * 2] : w32[idx];
        int flag = (t >= 1 && (tok == 1 || tok == 2)) ? 1 : 0;
        s[t] = flag;
        __syncthreads();
        #pragma unroll
        for (int off = 1; off < T_; off <<= 1) {
            int v = (t >= off) ? s[t - off] : 0;
            __syncthreads();
            s[t] += v;
            __syncthreads();
        }
        int jj;
        if (t == 0) jj = 0;
        else { jj = t - s[t] - 1; if (jj < 0) jj += S_; }
        d_j[idx] = jj;
    } else {
        // --- W -> fp16
        const int n = bid - B_;
        const size_t base = (size_t)n * K2_ + t;
        d_W16[base] = __float2half_rn(W[base]);
    }
}

// ---------------------------------------------------------------------------
// 2) prep: A -> fp16 (gathered [context | output] rows)
// ---------------------------------------------------------------------------
__global__ void prep_a_kernel(const float* __restrict__ outp,     // [M, D]
                              const float* __restrict__ context)  // [B, S, D]
{
    const int m = blockIdx.x;
    const int t = threadIdx.x;        // 256 threads x 4 floats = 1024 cols
    const int col = t * 4;
    const int bb = m >> 10;
    const int jm = d_j[m];
    const float* src = (t < 128)
        ? context + ((size_t)((bb << 10) + jm)) * D_ + col
        : outp + (size_t)m * D_ + (col - D_);
    float4 v = *(const float4*)src;
    union { __half2 h2[2]; uint2 u; } p;
    p.h2[0] = __floats2half2_rn(v.x, v.y);
    p.h2[1] = __floats2half2_rn(v.z, v.w);
    *(uint2*)(d_A16 + (size_t)m * K2_ + col) = p.u;
}

// ---------------------------------------------------------------------------
// 3) HMMA GEMM (single-pass fp16, fp32 accum) + fused attn one-hot writes:
//    out[m,n] = tanh(bias[n] + sum_k A[m,k]*W[n,k])
//    CTA 128x256, 8 warps 64x64, K-chunk 32, 5-stage pipeline, 1 sync/chunk.
//    blockIdx.x==0 CTAs also stream the one-hot attn rows (4 rows/chunk),
//    hidden in the pipeline's memory slack (GEMM uses ~4% of DRAM).
// ---------------------------------------------------------------------------
__global__ __launch_bounds__(NTHREADS, 1)
void gemm_mma_kernel(const float* __restrict__ bias, float* __restrict__ out,
                     float* __restrict__ attn)
{
    extern __shared__ char smem[];
    const uint32_t smb = smem_u32(smem);
    const int tid = threadIdx.x;
    const int wid = tid >> 5;
    const int lane = tid & 31;
    const int wm = wid & 1;           // warp m (2): 64 rows
    const int wn = wid >> 1;          // warp n (4): 64 cols
    const int m0 = blockIdx.y * BM;
    const int n0 = blockIdx.x * BN;
    const bool do_attn = (blockIdx.x == 0);

    float acc[4][8][4];
    #pragma unroll
    for (int i = 0; i < 4; i++)
        #pragma unroll
        for (int j = 0; j < 8; j++)
            #pragma unroll
            for (int k = 0; k < 4; k++) acc[i][j][k] = 0.f;

    // ---- loader: stage s <- chunk c (256 threads; 64B per row)
    auto issue = [&](int c, int s) {
        const int k0 = c * BKc;
        const uint32_t st = smb + s * STAGE_SZ;
        if (tid < 128) {
            const __half* src = d_A16 + (size_t)(m0 + tid) * K2_ + k0;
            const uint32_t dst = st + A_OFF + tid * A_ROW;
            cp16(dst,      src);
            cp16(dst + 16, src + 8);
            cp16(dst + 32, src + 16);
            cp16(dst + 48, src + 24);
        }
        {
            const __half* src = d_W16 + (size_t)(n0 + tid) * K2_ + k0;
            const uint32_t dst = st + W_OFF + tid * A_ROW;
            cp16(dst,      src);
            cp16(dst + 16, src + 8);
            cp16(dst + 32, src + 16);
            cp16(dst + 48, src + 24);
        }
    };

    // prologue: fill stages 0..3 (one stage of write slack)
    #pragma unroll
    for (int s = 0; s < NSTAGE - 1; s++) { issue(s, s); CP_COMMIT(); }

    // ldmatrix lane addressing
    const uint32_t aoff = (uint32_t)((wm * 64 + (lane & 15)) * A_ROW + (lane >> 4) * 16);
    const int g = lane >> 3;
    const uint32_t boff = (uint32_t)((wn * 64 + ((g >> 1) << 3) + (lane & 7)) * A_ROW
                                     + (g & 1) * 16);

    int stage = 0;
    int wstage = NSTAGE - 1;
    for (int c = 0; c < NCH; c++) {
        CP_WAIT(3);
        __syncthreads();
        // refill the stage consumed at iter c-1 (all warps passed the sync)
        if (c + NSTAGE - 1 < NCH) issue(c + NSTAGE - 1, wstage);
        CP_COMMIT();

        // fused attn writes: rows m0 + c*4 .. +3 (16KB, hidden in mem slack)
        if (do_attn) {
            const int row = m0 + (c << 2) + (tid >> 6);
            const int j = d_j[row];
            float4* dst = (float4*)(attn + (size_t)row * S_) + (tid & 63);
            #pragma unroll
            for (int q = 0; q < 4; q++) {
                float4 v = make_float4(0.f, 0.f, 0.f, 0.f);
                const int cb = (tid & 63) + q * 64;
                if ((j >> 2) == cb) ((float*)&v)[j & 3] = 1.0f;
                dst[q * 64] = v;
            }
        }

        const uint32_t st = smb + stage * STAGE_SZ;
        #pragma unroll
        for (int ks = 0; ks < 2; ks++) {
            const uint32_t kb = ks * 32;
            uint32_t a[4][4];
            #pragma unroll
            for (int mt = 0; mt < 4; mt++)
                ldsm4(a[mt], st + A_OFF + aoff + kb + mt * 16 * A_ROW);
            #pragma unroll
            for (int np = 0; np < 4; np++) {
                uint32_t b[4];
                ldsm4(b, st + W_OFF + boff + kb + np * 16 * A_ROW);
                #pragma unroll
                for (int mt = 0; mt < 4; mt++) {
                    mma16816(acc[mt][np * 2],     a[mt], b[0], b[1]);
                    mma16816(acc[mt][np * 2 + 1], a[mt], b[2], b[3]);
                }
            }
        }

        stage  = (stage  + 1 == NSTAGE) ? 0 : stage + 1;
        wstage = (wstage + 1 == NSTAGE) ? 0 : wstage + 1;
    }

    // ---- epilogue: bias + tanh, float2 stores
    const int r4 = lane >> 2;
    const int c2 = (lane & 3) * 2;
    #pragma unroll
    for (int mt = 0; mt < 4; mt++) {
        #pragma unroll
        for (int nt = 0; nt < 8; nt++) {
            const int gm = m0 + wm * 64 + mt * 16 + r4;
            const int gn = n0 + wn * 64 + nt * 8 + c2;
            const float b0 = bias[gn], b1 = bias[gn + 1];
            float2 v0, v1;
            v0.x = tanhf(acc[mt][nt][0] + b0);
            v0.y = tanhf(acc[mt][nt][1] + b1);
            v1.x = tanhf(acc[mt][nt][2] + b0);
            v1.y = tanhf(acc[mt][nt][3] + b1);
            *(float2*)(out + (size_t)gm * D_ + gn) = v0;
            *(float2*)(out + (size_t)(gm + 8) * D_ + gn) = v1;
        }
    }
}

// ---------------------------------------------------------------------------
extern "C" void kernel_launch(void* const* d_in, const int* in_sizes, int n_in,
                              void* d_out, int out_size) {
    const int* input_var = nullptr;
    const float* output  = nullptr;
    const float* context = nullptr;
    const float* W    = nullptr;
    const float* bias = nullptr;

    for (int i = 0; i < n_in; i++) {
        const int sz = in_sizes[i];
        if (sz == B_ * T_) input_var = (const int*)d_in[i];
        else if (sz == B_ * T_ * D_) {
            if (!output) output = (const float*)d_in[i];
            else if (!context) context = (const float*)d_in[i];
        } else if (sz == D_ * K2_) W = (const float*)d_in[i];
        else if (sz == D_) bias = (const float*)d_in[i];
    }

    float* out  = (float*)d_out;                 // [B,T,D]
    float* attn = out + (size_t)M_ * D_;         // [B,T,S]

    static bool attr_set = false;
    if (!attr_set) {
        cudaFuncSetAttribute(gemm_mma_kernel,
                             cudaFuncAttributeMaxDynamicSharedMemorySize, SMEM_TOTAL);
        attr_set = true;
    }

    prep_misc_kernel<<<B_ + D_, 1024>>>(input_var, W);
    prep_a_kernel<<<M_, 256>>>(output, context);
    dim3 grid(D_ / BN, M_ / BM);  // (2, 256)
    gemm_mma_kernel<<<grid, NTHREADS, SMEM_TOTAL>>>(bias, out, attn);
}

// round 12
// speedup vs baseline: 1.9230x; 1.0246x over previous
#include <cuda_runtime.h>
#include <cuda_fp16.h>
#include <cstdint>

#define B_  32
#define T_  1024
#define S_  1024
#define D_  512
#define K2_ 1024          // 2*D
#define M_  (B_ * T_)     // 32768

// GEMM tiling
#define BM 128
#define BN 128
#define BKc 32            // k per chunk (two m16n8k16 k-steps)
#define NCH (K2_ / BKc)   // 32 chunks
#define NSTAGE 5
#define NTHREADS 256

// smem layout (bytes, per stage): 64B data + 16B pad = 80B row stride
// (conflict-free ldsm: r*80 -> word offsets {0,20,8,28,16,4,24,12} mod 32)
#define A_ROW   80
#define A_OFF   0
#define W_OFF   (128 * A_ROW)             // 10240
#define STAGE_SZ (W_OFF + 128 * A_ROW)    // 20480
#define SMEM_TOTAL (NSTAGE * STAGE_SZ)    // 102400 -> 2 CTAs/SM

// ---------------------------------------------------------------------------
// device scratch (module globals)
// ---------------------------------------------------------------------------
__device__ int d_j[M_];
__device__ __align__(16) __half d_W16[D_ * K2_];
__device__ __align__(16) __half d_A16[(size_t)M_ * K2_];

// ---------------------------------------------------------------------------
// PTX helpers
// ---------------------------------------------------------------------------
__device__ __forceinline__ uint32_t smem_u32(const void* p) {
    uint32_t a;
    asm("{ .reg .u64 t; cvta.to.shared.u64 t, %1; cvt.u32.u64 %0, t; }"
        : "=r"(a) : "l"(p));
    return a;
}
__device__ __forceinline__ void cp16(uint32_t dst, const void* src) {
    asm volatile("cp.async.cg.shared.global [%0], [%1], 16;" :: "r"(dst), "l"(src));
}
#define CP_COMMIT() asm volatile("cp.async.commit_group;" ::: "memory")
#define CP_WAIT(n)  asm volatile("cp.async.wait_group %0;" :: "n"(n) : "memory")

__device__ __forceinline__ void ldsm4(uint32_t* r, uint32_t addr) {
    asm volatile("ldmatrix.sync.aligned.m8n8.x4.shared.b16 {%0,%1,%2,%3}, [%4];"
                 : "=r"(r[0]), "=r"(r[1]), "=r"(r[2]), "=r"(r[3]) : "r"(addr));
}
__device__ __forceinline__ void mma16816(float* c, const uint32_t* a,
                                         uint32_t b0, uint32_t b1) {
    asm volatile(
        "mma.sync.aligned.m16n8k16.row.col.f32.f16.f16.f32 "
        "{%0,%1,%2,%3}, {%4,%5,%6,%7}, {%8,%9}, {%0,%1,%2,%3};"
        : "+f"(c[0]), "+f"(c[1]), "+f"(c[2]), "+f"(c[3])
        : "r"(a[0]), "r"(a[1]), "r"(a[2]), "r"(a[3]), "r"(b0), "r"(b1));
}

// ---------------------------------------------------------------------------
// 1) merged: compute_j (blocks 0..31) + prep_w (blocks 32..543)
// ---------------------------------------------------------------------------
__global__ void prep_misc_kernel(const int* __restrict__ w32,
                                 const float* __restrict__ W) {
    const int bid = blockIdx.x;
    const int t = threadIdx.x;
    if (bid < B_) {
        // --- j indices (token buffer int32 or int64, detected on device)
        __shared__ int s[T_];
        __shared__ int is64_s;
        if (t == 0) {
            int allzero = 1;
            #pragma unroll
            for (int i = 1; i < 64; i += 2) allzero &= (w32[i] == 0);
            is64_s = allzero;
        }
        __syncthreads();
        const int idx = bid * T_ + t;
        const int tok = is64_s ? w32[idx * 2] : w32[idx];
        int flag = (t >= 1 && (tok == 1 || tok == 2)) ? 1 : 0;
        s[t] = flag;
        __syncthreads();
        #pragma unroll
        for (int off = 1; off < T_; off <<= 1) {
            int v = (t >= off) ? s[t - off] : 0;
            __syncthreads();
            s[t] += v;
            __syncthreads();
        }
        int jj;
        if (t == 0) jj = 0;
        else { jj = t - s[t] - 1; if (jj < 0) jj += S_; }
        d_j[idx] = jj;
    } else {
        // --- W -> fp16
        const int n = bid - B_;
        const size_t base = (size_t)n * K2_ + t;
        d_W16[base] = __float2half_rn(W[base]);
    }
}

// ---------------------------------------------------------------------------
// 2) prep: A -> fp16 (gathered [context | output] rows)
// ---------------------------------------------------------------------------
__global__ void prep_a_kernel(const float* __restrict__ outp,     // [M, D]
                              const float* __restrict__ context)  // [B, S, D]
{
    const int m = blockIdx.x;
    const int t = threadIdx.x;        // 256 threads x 4 floats = 1024 cols
    const int col = t * 4;
    const int bb = m >> 10;
    const int jm = d_j[m];
    const float* src = (t < 128)
        ? context + ((size_t)((bb << 10) + jm)) * D_ + col
        : outp + (size_t)m * D_ + (col - D_);
    float4 v = *(const float4*)src;
    union { __half2 h2[2]; uint2 u; } p;
    p.h2[0] = __floats2half2_rn(v.x, v.y);
    p.h2[1] = __floats2half2_rn(v.z, v.w);
    *(uint2*)(d_A16 + (size_t)m * K2_ + col) = p.u;
}

// ---------------------------------------------------------------------------
// 3) HMMA GEMM (single-pass fp16, fp32 accum) + fused attn one-hot writes:
//    out[m,n] = tanh(bias[n] + sum_k A[m,k]*W[n,k])
//    CTA 128x128, 8 warps 64x32, K-chunk 32, 5-stage pipeline, 1 sync/chunk,
//    2 CTAs/SM for latency hiding. x==0 CTAs stream the attn one-hot rows.
// ---------------------------------------------------------------------------
__global__ __launch_bounds__(NTHREADS, 2)
void gemm_mma_kernel(const float* __restrict__ bias, float* __restrict__ out,
                     float* __restrict__ attn)
{
    extern __shared__ char smem[];
    const uint32_t smb = smem_u32(smem);
    const int tid = threadIdx.x;
    const int wid = tid >> 5;
    const int lane = tid & 31;
    const int wm = wid & 1;           // warp m (2): 64 rows
    const int wn = wid >> 1;          // warp n (4): 32 cols
    const int m0 = blockIdx.y * BM;
    const int n0 = blockIdx.x * BN;
    const bool do_attn = (blockIdx.x == 0);

    float acc[4][4][4];
    #pragma unroll
    for (int i = 0; i < 4; i++)
        #pragma unroll
        for (int j = 0; j < 4; j++)
            #pragma unroll
            for (int k = 0; k < 4; k++) acc[i][j][k] = 0.f;

    // ---- loader: stage s <- chunk c; tids 0-127: A row, 128-255: W row
    auto issue = [&](int c, int s) {
        const int k0 = c * BKc;
        const uint32_t st = smb + s * STAGE_SZ;
        const int r = tid & 127;
        const __half* src = (tid < 128)
            ? d_A16 + (size_t)(m0 + r) * K2_ + k0
            : d_W16 + (size_t)(n0 + r) * K2_ + k0;
        const uint32_t dst = st + (tid < 128 ? A_OFF : W_OFF) + r * A_ROW;
        cp16(dst,      src);
        cp16(dst + 16, src + 8);
        cp16(dst + 32, src + 16);
        cp16(dst + 48, src + 24);
    };

    // prologue: fill stages 0..3 (one stage of write slack)
    #pragma unroll
    for (int s = 0; s < NSTAGE - 1; s++) { issue(s, s); CP_COMMIT(); }

    // ldmatrix lane addressing
    const uint32_t aoff = (uint32_t)((wm * 64 + (lane & 15)) * A_ROW + (lane >> 4) * 16);
    const int g = lane >> 3;
    const uint32_t boff = (uint32_t)((wn * 32 + ((g >> 1) << 3) + (lane & 7)) * A_ROW
                                     + (g & 1) * 16);

    int stage = 0;
    int wstage = NSTAGE - 1;
    for (int c = 0; c < NCH; c++) {
        CP_WAIT(3);
        __syncthreads();
        // refill the stage consumed at iter c-1 (all warps passed the sync)
        if (c + NSTAGE - 1 < NCH) issue(c + NSTAGE - 1, wstage);
        CP_COMMIT();

        // fused attn writes: rows m0 + c*4 .. +3 (16KB, hidden in mem slack)
        if (do_attn) {
            const int row = m0 + (c << 2) + (tid >> 6);
            const int j = d_j[row];
            float4* dst = (float4*)(attn + (size_t)row * S_) + (tid & 63);
            #pragma unroll
            for (int q = 0; q < 4; q++) {
                float4 v = make_float4(0.f, 0.f, 0.f, 0.f);
                const int cb = (tid & 63) + q * 64;
                if ((j >> 2) == cb) ((float*)&v)[j & 3] = 1.0f;
                dst[q * 64] = v;
            }
        }

        const uint32_t st = smb + stage * STAGE_SZ;
        #pragma unroll
        for (int ks = 0; ks < 2; ks++) {
            const uint32_t kb = ks * 32;
            uint32_t a[4][4];
            #pragma unroll
            for (int mt = 0; mt < 4; mt++)
                ldsm4(a[mt], st + A_OFF + aoff + kb + mt * 16 * A_ROW);
            #pragma unroll
            for (int np = 0; np < 2; np++) {
                uint32_t b[4];
                ldsm4(b, st + W_OFF + boff + kb + np * 16 * A_ROW);
                #pragma unroll
                for (int mt = 0; mt < 4; mt++) {
                    mma16816(acc[mt][np * 2],     a[mt], b[0], b[1]);
                    mma16816(acc[mt][np * 2 + 1], a[mt], b[2], b[3]);
                }
            }
        }

        stage  = (stage  + 1 == NSTAGE) ? 0 : stage + 1;
        wstage = (wstage + 1 == NSTAGE) ? 0 : wstage + 1;
    }

    // ---- epilogue: bias + tanh, float2 stores
    const int r4 = lane >> 2;
    const int c2 = (lane & 3) * 2;
    #pragma unroll
    for (int mt = 0; mt < 4; mt++) {
        #pragma unroll
        for (int nt = 0; nt < 4; nt++) {
            const int gm = m0 + wm * 64 + mt * 16 + r4;
            const int gn = n0 + wn * 32 + nt * 8 + c2;
            const float b0 = bias[gn], b1 = bias[gn + 1];
            float2 v0, v1;
            v0.x = tanhf(acc[mt][nt][0] + b0);
            v0.y = tanhf(acc[mt][nt][1] + b1);
            v1.x = tanhf(acc[mt][nt][2] + b0);
            v1.y = tanhf(acc[mt][nt][3] + b1);
            *(float2*)(out + (size_t)gm * D_ + gn) = v0;
            *(float2*)(out + (size_t)(gm + 8) * D_ + gn) = v1;
        }
    }
}

// ---------------------------------------------------------------------------
extern "C" void kernel_launch(void* const* d_in, const int* in_sizes, int n_in,
                              void* d_out, int out_size) {
    const int* input_var = nullptr;
    const float* output  = nullptr;
    const float* context = nullptr;
    const float* W    = nullptr;
    const float* bias = nullptr;

    for (int i = 0; i < n_in; i++) {
        const int sz = in_sizes[i];
        if (sz == B_ * T_) input_var = (const int*)d_in[i];
        else if (sz == B_ * T_ * D_) {
            if (!output) output = (const float*)d_in[i];
            else if (!context) context = (const float*)d_in[i];
        } else if (sz == D_ * K2_) W = (const float*)d_in[i];
        else if (sz == D_) bias = (const float*)d_in[i];
    }

    float* out  = (float*)d_out;                 // [B,T,D]
    float* attn = out + (size_t)M_ * D_;         // [B,T,S]

    static bool attr_set = false;
    if (!attr_set) {
        cudaFuncSetAttribute(gemm_mma_kernel,
                             cudaFuncAttributeMaxDynamicSharedMemorySize, SMEM_TOTAL);
        attr_set = true;
    }

    prep_misc_kernel<<<B_ + D_, 1024>>>(input_var, W);
    prep_a_kernel<<<M_, 256>>>(output, context);
    dim3 grid(D_ / BN, M_ / BM);  // (4, 256)
    gemm_mma_kernel<<<grid, NTHREADS, SMEM_TOTAL>>>(bias, out, attn);
}